// round 5
// baseline (speedup 1.0000x reference)
#include <cuda_runtime.h>

// Leapfrog (KDK), softened point mass: a = -q / (r*(r+1)^2 + 1e-12).
//
// v5: same launch shape as v4 (scalar, 2N threads), but ALL special functions
// via rsqrt.approx.f32 (the only approx op with a guaranteed 1:1 MUFU.RSQ
// mapping — R4's issue-slot accounting showed sqrt.approx/rcp.approx were
// expanding to ~9-instruction SASS sequences each):
//   u   = rsqrt(r2)            // 1/r        (1 MUFU)
//   r   = r2 * u               // sqrt(r2)   (1 FMUL)
//   den = fma(r, r2, r) + 2*r2 // r(r+1)^2   (2 FFMA)
//   inv = rsqrt(den*den)       // 1/den      (1 FMUL + 1 MUFU)
// => 2 MUFU + 11 fma-pipe per accel eval, zero fixup code.
//
// Inputs: d_in[0]=ts f32[N], d_in[1]=w0_lead f32[N,6], d_in[2]=w0_trail f32[N,6],
//         d_in[3]=n_steps i32. Output f32[2N,6]: row 2i=trail_i, 2i+1=lead_i.

__device__ __forceinline__ float rsqrt_ap(float x) {
    float r; asm("rsqrt.approx.f32 %0, %1;" : "=f"(r) : "f"(x)); return r;
}

// p += coef * accel(q); ncoef pre-negated (-coef) folds accel's sign.
__device__ __forceinline__ void kick(float& qx, float& qy, float& qz,
                                     float& px, float& py, float& pz,
                                     float ncoef) {
    float r2 = fmaf(qx, qx, fmaf(qy, qy, qz * qz));
    float u  = rsqrt_ap(r2);            // 1/r
    float r  = r2 * u;                  // r
    float t  = fmaf(r, r2, r);          // r*r2 + r
    float den = fmaf(2.0f, r2, t);      // r(r+1)^2
    float inv = rsqrt_ap(den * den);    // 1/den (den > 0)
    float sc = inv * ncoef;             // -coef/den
    px = fmaf(sc, qx, px);
    py = fmaf(sc, qy, py);
    pz = fmaf(sc, qz, pz);
}

__global__ void __launch_bounds__(256)
leapfrog_v5_kernel(const float* __restrict__ ts,
                   const float* __restrict__ w0_lead,
                   const float* __restrict__ w0_trail,
                   const int*   __restrict__ n_steps_ptr,
                   float* __restrict__ out,
                   int N) {
    int tid = blockIdx.x * blockDim.x + threadIdx.x;
    if (tid >= 2 * N) return;

    int b = (tid >= N) ? 1 : 0;        // 0 = trail, 1 = lead
    int i = tid - b * N;

    const float* __restrict__ w0 = b ? w0_lead : w0_trail;

    int n_steps = *n_steps_ptr;
    float t_f = ts[N - 1] + 0.001f;    // broadcast, L2-resident
    float dt  = (t_f - ts[i]) / (float)n_steps;
    float nhdt = -0.5f * dt;
    float ndt  = -dt;

    const float2* __restrict__ row = reinterpret_cast<const float2*>(w0 + 6 * i);
    float2 v0 = row[0];
    float2 v1 = row[1];
    float2 v2 = row[2];
    float qx = v0.x, qy = v0.y, qz = v1.x;
    float px = v1.y, py = v2.x, pz = v2.y;

    // KDK with fused interior kicks:
    //   half kick; (n-1) x (drift; full kick); drift; half kick.
    kick(qx, qy, qz, px, py, pz, nhdt);
    #pragma unroll 4
    for (int s = 0; s < n_steps - 1; ++s) {
        qx = fmaf(dt, px, qx);
        qy = fmaf(dt, py, qy);
        qz = fmaf(dt, pz, qz);
        kick(qx, qy, qz, px, py, pz, ndt);
    }
    qx = fmaf(dt, px, qx);
    qy = fmaf(dt, py, qy);
    qz = fmaf(dt, pz, qz);
    kick(qx, qy, qz, px, py, pz, nhdt);

    int orow = 2 * i + b;
    float2* __restrict__ orow_p = reinterpret_cast<float2*>(out + 6 * orow);
    orow_p[0] = make_float2(qx, qy);
    orow_p[1] = make_float2(qz, px);
    orow_p[2] = make_float2(py, pz);
}

extern "C" void kernel_launch(void* const* d_in, const int* in_sizes, int n_in,
                              void* d_out, int out_size) {
    const float* ts       = (const float*)d_in[0];
    const float* w0_lead  = (const float*)d_in[1];
    const float* w0_trail = (const float*)d_in[2];
    const int*   n_steps  = (const int*)d_in[3];
    float* out = (float*)d_out;

    int N = in_sizes[0];
    int total = 2 * N;
    int threads = 256;
    int blocks = (total + threads - 1) / threads;
    leapfrog_v5_kernel<<<blocks, threads>>>(ts, w0_lead, w0_trail, n_steps, out, N);
}

// round 6
// speedup vs baseline: 1.1604x; 1.1604x over previous
#include <cuda_runtime.h>

// Leapfrog (KDK), softened point mass: a = -q / (r*(r+1)^2 + 1e-12).
//
// v6 = v5 math (rsqrt-only MUFU path, fused interior kicks) + scheduling fixes:
//  - block=64 -> 2048 CTAs: 13-14 CTAs/SM (imbalance 3.7%) instead of 512x256
//    (3-4 CTAs/SM, imbalance 33%). Worst-SM issue demand 19K -> 16.6K cyc.
//  - warp-parity stagger: odd warps peel one interior step pre-loop, breaking
//    the MUFU convoy (all warps hitting rsqrt in lockstep bursts against
//    MUFU rt=8/SMSP while the FMA pipe idles, then vice versa).
//
// Inputs: d_in[0]=ts f32[N], d_in[1]=w0_lead f32[N,6], d_in[2]=w0_trail f32[N,6],
//         d_in[3]=n_steps i32. Output f32[2N,6]: row 2i=trail_i, 2i+1=lead_i.

__device__ __forceinline__ float rsqrt_ap(float x) {
    float r; asm("rsqrt.approx.f32 %0, %1;" : "=f"(r) : "f"(x)); return r;
}

// p += coef * accel(q); ncoef pre-negated (-coef) folds accel's sign.
__device__ __forceinline__ void kick(float& qx, float& qy, float& qz,
                                     float& px, float& py, float& pz,
                                     float ncoef) {
    float r2 = fmaf(qx, qx, fmaf(qy, qy, qz * qz));
    float u  = rsqrt_ap(r2);            // 1/r
    float r  = r2 * u;                  // r
    float t  = fmaf(r, r2, r);          // r*r2 + r
    float den = fmaf(2.0f, r2, t);      // r(r+1)^2
    float inv = rsqrt_ap(den * den);    // 1/den (den > 0)
    float sc = inv * ncoef;             // -coef/den
    px = fmaf(sc, qx, px);
    py = fmaf(sc, qy, py);
    pz = fmaf(sc, qz, pz);
}

__global__ void __launch_bounds__(64)
leapfrog_v6_kernel(const float* __restrict__ ts,
                   const float* __restrict__ w0_lead,
                   const float* __restrict__ w0_trail,
                   const int*   __restrict__ n_steps_ptr,
                   float* __restrict__ out,
                   int N) {
    int tid = blockIdx.x * blockDim.x + threadIdx.x;
    if (tid >= 2 * N) return;

    int b = (tid >= N) ? 1 : 0;        // 0 = trail, 1 = lead
    int i = tid - b * N;

    const float* __restrict__ w0 = b ? w0_lead : w0_trail;

    int n_steps = *n_steps_ptr;
    float t_f = ts[N - 1] + 0.001f;    // broadcast, L2-resident
    float dt  = (t_f - ts[i]) / (float)n_steps;
    float nhdt = -0.5f * dt;
    float ndt  = -dt;

    const float2* __restrict__ row = reinterpret_cast<const float2*>(w0 + 6 * i);
    float2 v0 = row[0];
    float2 v1 = row[1];
    float2 v2 = row[2];
    float qx = v0.x, qy = v0.y, qz = v1.x;
    float px = v1.y, py = v2.x, pz = v2.y;

    // KDK, fused interior kicks:
    //   half kick; (n-1) x (drift; full kick); drift; half kick.
    kick(qx, qy, qz, px, py, pz, nhdt);

    int rem = n_steps - 1;             // interior (drift + full kick) count

    // Stagger: odd warps run one interior step before the shared loop, so the
    // two parity groups execute offset phases of the step (MUFU vs FMA).
    if ((threadIdx.x >> 5) & 1) {
        qx = fmaf(dt, px, qx);
        qy = fmaf(dt, py, qy);
        qz = fmaf(dt, pz, qz);
        kick(qx, qy, qz, px, py, pz, ndt);
        rem -= 1;
    }

    #pragma unroll 4
    for (int s = 0; s < rem; ++s) {
        qx = fmaf(dt, px, qx);
        qy = fmaf(dt, py, qy);
        qz = fmaf(dt, pz, qz);
        kick(qx, qy, qz, px, py, pz, ndt);
    }

    qx = fmaf(dt, px, qx);
    qy = fmaf(dt, py, qy);
    qz = fmaf(dt, pz, qz);
    kick(qx, qy, qz, px, py, pz, nhdt);

    int orow = 2 * i + b;
    float2* __restrict__ orow_p = reinterpret_cast<float2*>(out + 6 * orow);
    orow_p[0] = make_float2(qx, qy);
    orow_p[1] = make_float2(qz, px);
    orow_p[2] = make_float2(py, pz);
}

extern "C" void kernel_launch(void* const* d_in, const int* in_sizes, int n_in,
                              void* d_out, int out_size) {
    const float* ts       = (const float*)d_in[0];
    const float* w0_lead  = (const float*)d_in[1];
    const float* w0_trail = (const float*)d_in[2];
    const int*   n_steps  = (const int*)d_in[3];
    float* out = (float*)d_out;

    int N = in_sizes[0];
    int total = 2 * N;
    int threads = 64;                   // 2048 CTAs -> balanced 13-14 per SM
    int blocks = (total + threads - 1) / threads;
    leapfrog_v6_kernel<<<blocks, threads>>>(ts, w0_lead, w0_trail, n_steps, out, N);
}

// round 7
// speedup vs baseline: 1.1633x; 1.0025x over previous
#include <cuda_runtime.h>

// Leapfrog (KDK), softened point mass: a = -q / (r*(r+1)^2 + 1e-12).
//
// v7 = v6 math/launch (rsqrt-only MUFU path, fused interior kicks, block=64,
// 2048 balanced CTAs) with the issue stream slimmed:
//  - n_steps==64 specialization (uniform device-side branch, generic
//    fallback): 63 interior steps FULLY unrolled -> zero loop ALU/branches,
//    straight-line body ptxas can schedule across step boundaries.
//  - dt via multiply by 1/64 (exact, power of two) -> no per-thread division.
//  - stagger removed (R6: no measurable effect).
//
// Inputs: d_in[0]=ts f32[N], d_in[1]=w0_lead f32[N,6], d_in[2]=w0_trail f32[N,6],
//         d_in[3]=n_steps i32. Output f32[2N,6]: row 2i=trail_i, 2i+1=lead_i.

__device__ __forceinline__ float rsqrt_ap(float x) {
    float r; asm("rsqrt.approx.f32 %0, %1;" : "=f"(r) : "f"(x)); return r;
}

// p += coef * accel(q); ncoef pre-negated (-coef) folds accel's sign.
__device__ __forceinline__ void kick(float& qx, float& qy, float& qz,
                                     float& px, float& py, float& pz,
                                     float ncoef) {
    float r2 = fmaf(qx, qx, fmaf(qy, qy, qz * qz));
    float u  = rsqrt_ap(r2);            // 1/r
    float r  = r2 * u;                  // r
    float t  = fmaf(r, r2, r);          // r*r2 + r
    float den = fmaf(2.0f, r2, t);      // r(r+1)^2
    float inv = rsqrt_ap(den * den);    // 1/den (den > 0)
    float sc = inv * ncoef;             // -coef/den
    px = fmaf(sc, qx, px);
    py = fmaf(sc, qy, py);
    pz = fmaf(sc, qz, pz);
}

__device__ __forceinline__ void drift(float& qx, float& qy, float& qz,
                                      float px, float py, float pz, float dt) {
    qx = fmaf(dt, px, qx);
    qy = fmaf(dt, py, qy);
    qz = fmaf(dt, pz, qz);
}

// KDK with fused interior kicks; INTERIOR = n_steps - 1 known at compile time
// on the hot path so the loop fully unrolls.
template <int INTERIOR, bool FULL_UNROLL>
__device__ __forceinline__ void integrate(float& qx, float& qy, float& qz,
                                          float& px, float& py, float& pz,
                                          float dt, int interior_rt) {
    float nhdt = -0.5f * dt;
    float ndt  = -dt;

    kick(qx, qy, qz, px, py, pz, nhdt);
    if (FULL_UNROLL) {
        #pragma unroll
        for (int s = 0; s < INTERIOR; ++s) {
            drift(qx, qy, qz, px, py, pz, dt);
            kick(qx, qy, qz, px, py, pz, ndt);
        }
    } else {
        #pragma unroll 4
        for (int s = 0; s < interior_rt; ++s) {
            drift(qx, qy, qz, px, py, pz, dt);
            kick(qx, qy, qz, px, py, pz, ndt);
        }
    }
    drift(qx, qy, qz, px, py, pz, dt);
    kick(qx, qy, qz, px, py, pz, nhdt);
}

__global__ void __launch_bounds__(64)
leapfrog_v7_kernel(const float* __restrict__ ts,
                   const float* __restrict__ w0_lead,
                   const float* __restrict__ w0_trail,
                   const int*   __restrict__ n_steps_ptr,
                   float* __restrict__ out,
                   int N) {
    int tid = blockIdx.x * blockDim.x + threadIdx.x;
    if (tid >= 2 * N) return;

    int b = (tid >= N) ? 1 : 0;        // 0 = trail, 1 = lead
    int i = tid - b * N;

    const float* __restrict__ w0 = b ? w0_lead : w0_trail;

    int n_steps = *n_steps_ptr;
    float t_f = ts[N - 1] + 0.001f;    // broadcast, L2-resident

    const float2* __restrict__ row = reinterpret_cast<const float2*>(w0 + 6 * i);
    float2 v0 = row[0];
    float2 v1 = row[1];
    float2 v2 = row[2];
    float qx = v0.x, qy = v0.y, qz = v1.x;
    float px = v1.y, py = v2.x, pz = v2.y;

    if (n_steps == 64) {
        float dt = (t_f - ts[i]) * 0.015625f;   // exact /64
        integrate<63, true>(qx, qy, qz, px, py, pz, dt, 63);
    } else {
        float dt = (t_f - ts[i]) / (float)n_steps;
        integrate<0, false>(qx, qy, qz, px, py, pz, dt, n_steps - 1);
    }

    int orow = 2 * i + b;
    float2* __restrict__ orow_p = reinterpret_cast<float2*>(out + 6 * orow);
    orow_p[0] = make_float2(qx, qy);
    orow_p[1] = make_float2(qz, px);
    orow_p[2] = make_float2(py, pz);
}

extern "C" void kernel_launch(void* const* d_in, const int* in_sizes, int n_in,
                              void* d_out, int out_size) {
    const float* ts       = (const float*)d_in[0];
    const float* w0_lead  = (const float*)d_in[1];
    const float* w0_trail = (const float*)d_in[2];
    const int*   n_steps  = (const int*)d_in[3];
    float* out = (float*)d_out;

    int N = in_sizes[0];
    int total = 2 * N;
    int threads = 64;                   // 2048 CTAs -> balanced 13-14 per SM
    int blocks = (total + threads - 1) / threads;
    leapfrog_v7_kernel<<<blocks, threads>>>(ts, w0_lead, w0_trail, n_steps, out, N);
}